// round 12
// baseline (speedup 1.0000x reference)
#include <cuda_runtime.h>
#include <cuda_bf16.h>
#include <cstdint>

#define NN 2048
#define TJ 32
#define SPLIT 8
#define JCHUNK (NN / SPLIT)      // 256
#define NTILES (JCHUNK / TJ)     // 8

typedef unsigned long long ull;

// Scratch (device globals; no allocation allowed)
__device__ float g_h   [2 * NN * 128];          // h[b][n][128]
__device__ float g_v   [2 * NN * 128];          // vperm[b][j][h*32+d], tf32-rounded
__device__ float g_ei  [2 * NN * 4];
__device__ float g_ej  [2 * NN * 4];
__device__ float g_part[SPLIT * 2 * NN * 128];  // partial AV accumulators
__device__ float g_psum[SPLIT * 2 * NN * 4];    // partial softmax denominators

__device__ __forceinline__ float tf32r(float x) {
    uint32_t u;
    asm("cvt.rna.tf32.f32 %0, %1;" : "=r"(u) : "f"(x));
    return __uint_as_float(u);
}

// dynamic smem layout (bytes): 64-row mask tile
#define VSM_OFF 0
#define VSM_BUF (TJ * 136 * 4)          // 17408
#define MSM_OFF (2 * VSM_BUF)           // 34816
#define MSM_BUF (64 * 36 * 4)           // 9216
#define EJS_OFF (MSM_OFF + 2 * MSM_BUF) // 53248
#define EJS_BUF (TJ * 4 * 4)            // 512
#define SMEM_SZ (EJS_OFF + 2 * EJS_BUF) // 54272

// ---------------------------------------------------------------------------
// Kernel 1: h = x @ w^T, scatter permuted v (tf32-rounded), compute ei/ej.
// ---------------------------------------------------------------------------
__global__ __launch_bounds__(128) void k1_proj(const float* __restrict__ x,
                                               const float* __restrict__ w,
                                               const float* __restrict__ a) {
    const int t    = threadIdx.x;
    const int r0   = blockIdx.x * 8;
    const int h    = t >> 5;
    const int d    = t & 31;
    const int lane = t & 31;

    __shared__ float ws[128 * 65];
    __shared__ float xs[8 * 64];

#pragma unroll
    for (int k = 0; k < 64; ++k) {
        int idx = t + k * 128;
        ws[(idx >> 6) * 65 + (idx & 63)] = w[idx];
    }
#pragma unroll
    for (int k = 0; k < 4; ++k)
        xs[t + k * 128] = x[r0 * 64 + t + k * 128];
    __syncthreads();

    const float a1v = a[h * 64 + d];
    const float a2v = a[h * 64 + 32 + d];
    const float* wrow = &ws[t * 65];

    for (int rr = 0; rr < 8; ++rr) {
        const int row = r0 + rr;
        float acc = 0.f;
#pragma unroll
        for (int i = 0; i < 64; ++i)
            acc += xs[rr * 64 + i] * wrow[i];

        g_h[row * 128 + t] = acc;

        const int b   = row >> 11;
        const int n   = row & (NN - 1);
        const int idx = h * NN + n;
        g_v[(b * NN + (idx >> 2)) * 128 + (idx & 3) * 32 + d] = tf32r(acc);

        float p1 = acc * a1v;
        float p2 = acc * a2v;
#pragma unroll
        for (int off = 16; off; off >>= 1) {
            p1 += __shfl_xor_sync(0xffffffffu, p1, off);
            p2 += __shfl_xor_sync(0xffffffffu, p2, off);
        }
        if (lane == 0) {
            g_ei[row * 4 + h] = p1;
            g_ej[row * 4 + h] = p2;
        }
    }
}

// ---------------------------------------------------------------------------
// Kernel 2: attention via tf32 mma.sync.m16n8k8, double-buffered cp.async.
// Grid 512 = sp(8) x nt(32, 64-row tiles) x b(2); 256 threads = 8 warps;
// warp = (row-group rg = wp&3 [16 rows], head-pair hp = wp>>2 [2 heads]).
// acc = 32 regs/thread -> 3 CTAs/SM (6 warps/SMSP). P computed directly
// into A-frags; V + mask prefetched one tile ahead.
// ---------------------------------------------------------------------------
__global__ __launch_bounds__(256, 3) void k2_attn(const int* __restrict__ adj) {
    extern __shared__ __align__(16) char smem[];
    const int t  = threadIdx.x;
    const int wp = t >> 5;
    const int qr = (t & 31) >> 2;
    const int qc = t & 3;
    const int rg = wp & 3;                  // row group: rows rg*16..rg*16+15
    const int hp = wp >> 2;                 // head pair: heads 2hp, 2hp+1
    const int sp = blockIdx.x & 7;
    const int nt = (blockIdx.x >> 3) & 31;
    const int b  = blockIdx.x >> 8;
    const int n0 = nt * 64;
    const int js = sp * JCHUNK;
    const int r0 = rg * 16;

    const float2 eiA = *(const float2*)&g_ei[(size_t)(b * NN + n0 + r0 + qr) * 4 + hp * 2];
    const float2 eiB = *(const float2*)&g_ei[(size_t)(b * NN + n0 + r0 + 8 + qr) * 4 + hp * 2];

    float acc[8][4];                        // [h2*4+n][c0..c3]
#pragma unroll
    for (int i = 0; i < 8; ++i)
#pragma unroll
        for (int j = 0; j < 4; ++j) acc[i][j] = 0.f;
    float ps0[2], ps1[2];
#pragma unroll
    for (int h = 0; h < 2; ++h) { ps0[h] = 0.f; ps1[h] = 0.f; }

    uint32_t sbase;
    asm("{ .reg .u64 u; cvta.to.shared.u64 u, %1; cvt.u32.u64 %0, u; }" : "=r"(sbase) : "l"(smem));

    // tile loader: V 32x128 floats (4/thread), mask 64x32 ints (2/thread)
    auto issue = [&](int tile) {
        const int j0  = js + tile * TJ;
        const int buf = tile & 1;
        const uint32_t vbase = sbase + VSM_OFF + buf * VSM_BUF;
        const uint32_t mbase = sbase + MSM_OFF + buf * MSM_BUF;
#pragma unroll
        for (int k = 0; k < 4; ++k) {
            int c = t + k * 256;
            int row = c >> 5, o = c & 31;
            uint32_t dst = vbase + row * 544 + o * 16;
            const float* src = g_v + (size_t)(b * NN + j0 + row) * 128 + o * 4;
            asm volatile("cp.async.cg.shared.global [%0], [%1], 16;" :: "r"(dst), "l"(src));
        }
#pragma unroll
        for (int k = 0; k < 2; ++k) {
            int c = t + k * 256;
            int row = c >> 3, o = c & 7;
            uint32_t dst = mbase + row * 144 + o * 16;
            const int* src = adj + (size_t)(n0 + row) * NN + j0 + o * 4;
            asm volatile("cp.async.cg.shared.global [%0], [%1], 16;" :: "r"(dst), "l"(src));
        }
        if (t < TJ)
            *(float4*)(smem + EJS_OFF + buf * EJS_BUF + t * 16)
                = *(const float4*)&g_ej[(size_t)(b * NN + j0 + t) * 4];
        asm volatile("cp.async.commit_group;");
    };

    issue(0);

    for (int tile = 0; tile < NTILES; ++tile) {
        const int buf = tile & 1;
        const float* vsm = (const float*)(smem + VSM_OFF + buf * VSM_BUF);
        const int*   msm = (const int*)  (smem + MSM_OFF + buf * MSM_BUF);
        const float* ejs = (const float*)(smem + EJS_OFF + buf * EJS_BUF);

        if (tile + 1 < NTILES) {
            issue(tile + 1);
            asm volatile("cp.async.wait_group 1;" ::: "memory");
        } else {
            asm volatile("cp.async.wait_group 0;" ::: "memory");
        }
        __syncthreads();

#pragma unroll
        for (int ks = 0; ks < 4; ++ks) {
            const int jc = ks * 8 + qc;
            const int m0 = msm[(r0 + qr) * 36 + jc];
            const int m1 = msm[(r0 + 8 + qr) * 36 + jc];
            const int m2 = msm[(r0 + qr) * 36 + jc + 4];
            const int m3 = msm[(r0 + 8 + qr) * 36 + jc + 4];
            const float2 ejA = *(const float2*)&ejs[jc * 4 + hp * 2];
            const float2 ejB = *(const float2*)&ejs[(jc + 4) * 4 + hp * 2];
#pragma unroll
            for (int h = 0; h < 2; ++h) {
                const float ei0 = (&eiA.x)[h], ei1 = (&eiB.x)[h];
                const float ej0 = (&ejA.x)[h], ej1 = (&ejB.x)[h];
                float e, p;
                uint32_t a0, a1, a2, a3;
                e = ei0 + ej0; e = fmaxf(e, 0.2f * e);
                p = m0 ? tf32r(__expf(e)) : 0.f; ps0[h] += p; a0 = __float_as_uint(p);
                e = ei1 + ej0; e = fmaxf(e, 0.2f * e);
                p = m1 ? tf32r(__expf(e)) : 0.f; ps1[h] += p; a1 = __float_as_uint(p);
                e = ei0 + ej1; e = fmaxf(e, 0.2f * e);
                p = m2 ? tf32r(__expf(e)) : 0.f; ps0[h] += p; a2 = __float_as_uint(p);
                e = ei1 + ej1; e = fmaxf(e, 0.2f * e);
                p = m3 ? tf32r(__expf(e)) : 0.f; ps1[h] += p; a3 = __float_as_uint(p);
#pragma unroll
                for (int n = 0; n < 4; ++n) {
                    const int col = hp * 64 + h * 32 + n * 8 + qr;
                    uint32_t b0 = __float_as_uint(vsm[jc * 136 + col]);
                    uint32_t b1 = __float_as_uint(vsm[(jc + 4) * 136 + col]);
                    float* c = acc[h * 4 + n];
                    asm("mma.sync.aligned.m16n8k8.row.col.f32.tf32.tf32.f32 "
                        "{%0,%1,%2,%3}, {%4,%5,%6,%7}, {%8,%9}, {%0,%1,%2,%3};"
                        : "+f"(c[0]), "+f"(c[1]), "+f"(c[2]), "+f"(c[3])
                        : "r"(a0), "r"(a1), "r"(a2), "r"(a3), "r"(b0), "r"(b1));
                }
            }
        }
        __syncthreads();   // buffer tile&1 free for reuse by issue(tile+2)
    }

    // psum: reduce over qc (lanes covering disjoint j); head-pair slice
#pragma unroll
    for (int h = 0; h < 2; ++h) {
        ps0[h] += __shfl_xor_sync(0xffffffffu, ps0[h], 1);
        ps0[h] += __shfl_xor_sync(0xffffffffu, ps0[h], 2);
        ps1[h] += __shfl_xor_sync(0xffffffffu, ps1[h], 1);
        ps1[h] += __shfl_xor_sync(0xffffffffu, ps1[h], 2);
    }
    if (qc == 0) {
        size_t base = ((size_t)(sp * 2 + b) * NN + n0 + r0);
        *(float2*)&g_psum[(base + qr) * 4 + hp * 2]     = make_float2(ps0[0], ps0[1]);
        *(float2*)&g_psum[(base + 8 + qr) * 4 + hp * 2] = make_float2(ps1[0], ps1[1]);
    }

    // accumulator writeback
    {
        size_t base0 = ((size_t)(sp * 2 + b) * NN + n0 + r0 + qr) * 128;
        size_t base1 = base0 + 8 * 128;
#pragma unroll
        for (int h = 0; h < 2; ++h)
#pragma unroll
            for (int n = 0; n < 4; ++n) {
                const int col = hp * 64 + h * 32 + n * 8 + qc * 2;
                const float* c = acc[h * 4 + n];
                *(float2*)&g_part[base0 + col] = make_float2(c[0], c[1]);
                *(float2*)&g_part[base1 + col] = make_float2(c[2], c[3]);
            }
    }
}

// ---------------------------------------------------------------------------
// Kernel 3: reduce split partials, normalize, residual, LayerNorm.
// ---------------------------------------------------------------------------
__global__ __launch_bounds__(128) void k3_epi(const float* __restrict__ gamma,
                                              const float* __restrict__ beta,
                                              float*       __restrict__ out) {
    const int t  = threadIdx.x;
    const int b  = blockIdx.x >> 8;
    const int n0 = (blockIdx.x & 255) * 8;
    const int h  = t >> 5;
    const int d  = t & 31;

    __shared__ float red1[4][8], red2[4][8];

    const float gma = gamma[t];
    const float bta = beta[t];
    float ys[8];

#pragma unroll
    for (int r = 0; r < 8; ++r) {
        const int n = n0 + r;
        float accv = 0.f, rsum = 0.f;
#pragma unroll
        for (int spp = 0; spp < SPLIT; ++spp) {
            accv += g_part[(size_t)((spp * 2 + b) * NN + n) * 128 + t];
            rsum += g_psum[((size_t)(spp * 2 + b) * NN + n) * 4 + h];
        }
        float y = accv / rsum + g_h[(size_t)(b * NN + n) * 128 + t];
        ys[r] = y;
        float s1 = y, s2 = y * y;
#pragma unroll
        for (int off = 16; off; off >>= 1) {
            s1 += __shfl_xor_sync(0xffffffffu, s1, off);
            s2 += __shfl_xor_sync(0xffffffffu, s2, off);
        }
        if (d == 0) { red1[h][r] = s1; red2[h][r] = s2; }
    }
    __syncthreads();
#pragma unroll
    for (int r = 0; r < 8; ++r) {
        float s1 = red1[0][r] + red1[1][r] + red1[2][r] + red1[3][r];
        float s2 = red2[0][r] + red2[1][r] + red2[2][r] + red2[3][r];
        float mu  = s1 * (1.f / 128.f);
        float var = s2 * (1.f / 128.f) - mu * mu;
        float inv = rsqrtf(var + 1e-5f);
        out[(size_t)(b * NN + n0 + r) * 128 + t] = (ys[r] - mu) * inv * gma + bta;
    }
}

extern "C" void kernel_launch(void* const* d_in, const int* in_sizes, int n_in,
                              void* d_out, int out_size) {
    const float* x     = (const float*)d_in[0];
    const int*   adj   = (const int*)  d_in[1];
    const float* w     = (const float*)d_in[2];
    const float* a     = (const float*)d_in[3];
    const float* gamma = (const float*)d_in[4];
    const float* beta  = (const float*)d_in[5];

    static int smem_set = 0;
    if (!smem_set) {
        cudaFuncSetAttribute(k2_attn, cudaFuncAttributeMaxDynamicSharedMemorySize, SMEM_SZ);
        smem_set = 1;
    }

    k1_proj<<<512, 128>>>(x, w, a);
    k2_attn<<<32 * SPLIT * 2, 256, SMEM_SZ>>>(adj);
    k3_epi<<<512, 128>>>(gamma, beta, (float*)d_out);
}

// round 13
// speedup vs baseline: 1.2120x; 1.2120x over previous
#include <cuda_runtime.h>
#include <cuda_bf16.h>
#include <cstdint>

#define NN 2048
#define TJ 32
#define SPLIT 8
#define JCHUNK (NN / SPLIT)      // 256
#define NTILES (JCHUNK / TJ)     // 8
#define LOG2E 1.4426950408889634f

typedef unsigned long long ull;

// Scratch (device globals; no allocation allowed)
__device__ float    g_h   [2 * NN * 128];          // h[b][n][128] fp32 (residual)
__device__ uint32_t g_vb  [2 * 1024 * 128];        // vperm bf16x2 j-pairs [b][jp][col]
__device__ float    g_ei  [2 * NN * 4];            // pre-scaled by log2(e)
__device__ float    g_ej  [2 * NN * 4];            // pre-scaled by log2(e)
__device__ float    g_part[SPLIT * 2 * NN * 128];  // partial AV accumulators
__device__ float    g_psum[SPLIT * 2 * NN * 4];    // partial softmax denominators

__device__ __forceinline__ float ex2(float x) {
    float r;
    asm("ex2.approx.f32 %0, %1;" : "=f"(r) : "f"(x));
    return r;
}
__device__ __forceinline__ uint32_t bf16x2(float hi, float lo) {
    uint32_t r;
    asm("cvt.rn.bf16x2.f32 %0, %1, %2;" : "=r"(r) : "f"(hi), "f"(lo));
    return r;
}

// dynamic smem layout (bytes):
#define VSM_BUF (16 * 136 * 4)          // 8704 (16 jp-rows x 136 u32 pitch)
#define MSM_OFF (2 * VSM_BUF)           // 17408
#define MSM_BUF (128 * 36 * 4)          // 18432
#define EJS_OFF (MSM_OFF + 2 * MSM_BUF) // 54272
#define EJS_BUF (TJ * 4 * 4)            // 512
#define SMEM_SZ (EJS_OFF + 2 * EJS_BUF) // 55296

// ---------------------------------------------------------------------------
// Kernel 1: h = x @ w^T, scatter permuted v as bf16x2 j-pairs, ei/ej (log2e).
// Thread t handles col (h,d); rows rr and rr+4 form exactly one vb pair.
// ---------------------------------------------------------------------------
__global__ __launch_bounds__(128) void k1_proj(const float* __restrict__ x,
                                               const float* __restrict__ w,
                                               const float* __restrict__ a) {
    const int t    = threadIdx.x;
    const int r0   = blockIdx.x * 8;
    const int h    = t >> 5;
    const int d    = t & 31;
    const int lane = t & 31;

    __shared__ float ws[128 * 65];
    __shared__ float xs[8 * 64];

#pragma unroll
    for (int k = 0; k < 64; ++k) {
        int idx = t + k * 128;
        ws[(idx >> 6) * 65 + (idx & 63)] = w[idx];
    }
#pragma unroll
    for (int k = 0; k < 4; ++k)
        xs[t + k * 128] = x[r0 * 64 + t + k * 128];
    __syncthreads();

    const float a1v = a[h * 64 + d];
    const float a2v = a[h * 64 + 32 + d];
    const float* wrow = &ws[t * 65];

    float accv[8];
    for (int rr = 0; rr < 8; ++rr) {
        const int row = r0 + rr;
        float acc = 0.f;
#pragma unroll
        for (int i = 0; i < 64; ++i)
            acc += xs[rr * 64 + i] * wrow[i];
        accv[rr] = acc;
        g_h[row * 128 + t] = acc;

        float p1 = acc * a1v;
        float p2 = acc * a2v;
#pragma unroll
        for (int off = 16; off; off >>= 1) {
            p1 += __shfl_xor_sync(0xffffffffu, p1, off);
            p2 += __shfl_xor_sync(0xffffffffu, p2, off);
        }
        if (lane == 0) {
            g_ei[row * 4 + h] = p1 * LOG2E;
            g_ej[row * 4 + h] = p2 * LOG2E;
        }
    }

    // vb pack: idx = h*NN + n0 + rr; pair rows (2jp,2jp+1) <- rr and rr+4
    const int b  = r0 >> 11;
    const int n0 = r0 & (NN - 1);
    const int jp = (h * NN + n0) >> 3;
#pragma unroll
    for (int rr = 0; rr < 4; ++rr)
        g_vb[(size_t)(b * 1024 + jp) * 128 + rr * 32 + d] = bf16x2(accv[rr + 4], accv[rr]);
}

// ---------------------------------------------------------------------------
// Kernel 2: attention via bf16 mma.sync.m16n8k16, double-buffered cp.async.
// Grid 256 = sp(8) x nt(16) x b(2), 256 threads = 8 warps x 16 rows.
// P computed into bf16x2 A-frags (never in smem); V bf16x2 pairs + adj mask
// prefetched one tile ahead; 64 fp32 accumulators persist across 256 j.
// m16n8k16 frags (lane = qr*4+qc):
//   A: a0={(qr,2qc),(qr,2qc+1)} a1={qr+8,..} a2={(qr,2qc+8),(qr,2qc+9)} a3={qr+8,..}
//   B: b0={(2qc,qr),(2qc+1,qr)} b1={(2qc+8,qr),(2qc+9,qr)}   (packed j-pairs)
//   C: c0=(qr,2qc) c1=(qr,2qc+1) c2=(qr+8,2qc) c3=(qr+8,2qc+1)
// ---------------------------------------------------------------------------
__global__ __launch_bounds__(256, 2) void k2_attn(const int* __restrict__ adj) {
    extern __shared__ __align__(16) char smem[];
    const int t  = threadIdx.x;
    const int wp = t >> 5;
    const int qr = (t & 31) >> 2;
    const int qc = t & 3;
    const int sp = blockIdx.x & 7;
    const int nt = (blockIdx.x >> 3) & 15;
    const int b  = blockIdx.x >> 7;
    const int n0 = nt * 128;
    const int js = sp * JCHUNK;
    const int r0 = wp * 16;

    const float4 eiA = *(const float4*)&g_ei[(size_t)(b * NN + n0 + r0 + qr) * 4];
    const float4 eiB = *(const float4*)&g_ei[(size_t)(b * NN + n0 + r0 + 8 + qr) * 4];

    float acc[16][4];
#pragma unroll
    for (int i = 0; i < 16; ++i)
#pragma unroll
        for (int j = 0; j < 4; ++j) acc[i][j] = 0.f;
    float ps0[4], ps1[4];
#pragma unroll
    for (int h = 0; h < 4; ++h) { ps0[h] = 0.f; ps1[h] = 0.f; }

    uint32_t sbase;
    asm("{ .reg .u64 u; cvta.to.shared.u64 u, %1; cvt.u32.u64 %0, u; }" : "=r"(sbase) : "l"(smem));

    // tile loader: V bf16x2 16x512B (2 chunks/thread), mask 128x128B (4/thread)
    auto issue = [&](int tile) {
        const int j0  = js + tile * TJ;
        const int jp0 = j0 >> 1;
        const int buf = tile & 1;
        const uint32_t vbase = sbase + buf * VSM_BUF;
        const uint32_t mbase = sbase + MSM_OFF + buf * MSM_BUF;
#pragma unroll
        for (int k = 0; k < 2; ++k) {
            int c = t + k * 256;            // 0..511
            int row = c >> 5, o = c & 31;
            uint32_t dst = vbase + row * 544 + o * 16;
            const uint32_t* src = g_vb + (size_t)(b * 1024 + jp0 + row) * 128 + o * 4;
            asm volatile("cp.async.cg.shared.global [%0], [%1], 16;" :: "r"(dst), "l"(src));
        }
#pragma unroll
        for (int k = 0; k < 4; ++k) {
            int c = t + k * 256;
            int row = c >> 3, o = c & 7;
            uint32_t dst = mbase + row * 144 + o * 16;
            const int* src = adj + (size_t)(n0 + row) * NN + j0 + o * 4;
            asm volatile("cp.async.cg.shared.global [%0], [%1], 16;" :: "r"(dst), "l"(src));
        }
        if (t < TJ)
            *(float4*)(smem + EJS_OFF + buf * EJS_BUF + t * 16)
                = *(const float4*)&g_ej[(size_t)(b * NN + j0 + t) * 4];
        asm volatile("cp.async.commit_group;");
    };

    issue(0);

    for (int tile = 0; tile < NTILES; ++tile) {
        const int buf = tile & 1;
        const uint32_t* vb  = (const uint32_t*)(smem + buf * VSM_BUF);
        const int*     msm  = (const int*)(smem + MSM_OFF + buf * MSM_BUF);
        const float4*  ejs4 = (const float4*)(smem + EJS_OFF + buf * EJS_BUF);

        if (tile + 1 < NTILES) {
            issue(tile + 1);
            asm volatile("cp.async.wait_group 1;" ::: "memory");
        } else {
            asm volatile("cp.async.wait_group 0;" ::: "memory");
        }
        __syncthreads();

#pragma unroll
        for (int ks = 0; ks < 2; ++ks) {
            const int jb = ks * 16;
            const int2 mA0 = *(const int2*)&msm[(r0 + qr) * 36 + jb + 2 * qc];
            const int2 mA1 = *(const int2*)&msm[(r0 + qr) * 36 + jb + 2 * qc + 8];
            const int2 mB0 = *(const int2*)&msm[(r0 + 8 + qr) * 36 + jb + 2 * qc];
            const int2 mB1 = *(const int2*)&msm[(r0 + 8 + qr) * 36 + jb + 2 * qc + 8];
            const float4 ej0 = ejs4[jb + 2 * qc];
            const float4 ej1 = ejs4[jb + 2 * qc + 1];
            const float4 ej2 = ejs4[jb + 2 * qc + 8];
            const float4 ej3 = ejs4[jb + 2 * qc + 9];
#pragma unroll
            for (int h = 0; h < 4; ++h) {
                const float ei0 = (&eiA.x)[h], ei1 = (&eiB.x)[h];
                const float ejv0 = (&ej0.x)[h], ejv1 = (&ej1.x)[h];
                const float ejv2 = (&ej2.x)[h], ejv3 = (&ej3.x)[h];
                float e;
                float pA0, pA1, pA2, pA3, pB0, pB1, pB2, pB3;
                e = ei0 + ejv0; e = fmaxf(e, 0.2f * e); pA0 = mA0.x ? ex2(e) : 0.f;
                e = ei0 + ejv1; e = fmaxf(e, 0.2f * e); pA1 = mA0.y ? ex2(e) : 0.f;
                e = ei0 + ejv2; e = fmaxf(e, 0.2f * e); pA2 = mA1.x ? ex2(e) : 0.f;
                e = ei0 + ejv3; e = fmaxf(e, 0.2f * e); pA3 = mA1.y ? ex2(e) : 0.f;
                e = ei1 + ejv0; e = fmaxf(e, 0.2f * e); pB0 = mB0.x ? ex2(e) : 0.f;
                e = ei1 + ejv1; e = fmaxf(e, 0.2f * e); pB1 = mB0.y ? ex2(e) : 0.f;
                e = ei1 + ejv2; e = fmaxf(e, 0.2f * e); pB2 = mB1.x ? ex2(e) : 0.f;
                e = ei1 + ejv3; e = fmaxf(e, 0.2f * e); pB3 = mB1.y ? ex2(e) : 0.f;
                ps0[h] += (pA0 + pA1) + (pA2 + pA3);
                ps1[h] += (pB0 + pB1) + (pB2 + pB3);
                const uint32_t a0 = bf16x2(pA1, pA0);
                const uint32_t a1 = bf16x2(pB1, pB0);
                const uint32_t a2 = bf16x2(pA3, pA2);
                const uint32_t a3 = bf16x2(pB3, pB2);
#pragma unroll
                for (int n = 0; n < 4; ++n) {
                    const int col = h * 32 + n * 8 + qr;
                    const uint32_t b0 = vb[(ks * 8 + qc) * 136 + col];
                    const uint32_t b1 = vb[(ks * 8 + qc + 4) * 136 + col];
                    float* c = acc[h * 4 + n];
                    asm("mma.sync.aligned.m16n8k16.row.col.f32.bf16.bf16.f32 "
                        "{%0,%1,%2,%3}, {%4,%5,%6,%7}, {%8,%9}, {%0,%1,%2,%3};"
                        : "+f"(c[0]), "+f"(c[1]), "+f"(c[2]), "+f"(c[3])
                        : "r"(a0), "r"(a1), "r"(a2), "r"(a3), "r"(b0), "r"(b1));
                }
            }
        }
        __syncthreads();   // buffer tile&1 free for reuse by issue(tile+2)
    }

    // psum: reduce over qc (lanes cover disjoint j)
#pragma unroll
    for (int h = 0; h < 4; ++h) {
        ps0[h] += __shfl_xor_sync(0xffffffffu, ps0[h], 1);
        ps0[h] += __shfl_xor_sync(0xffffffffu, ps0[h], 2);
        ps1[h] += __shfl_xor_sync(0xffffffffu, ps1[h], 1);
        ps1[h] += __shfl_xor_sync(0xffffffffu, ps1[h], 2);
    }
    if (qc == 0) {
        size_t base = ((size_t)(sp * 2 + b) * NN + n0 + r0);
        *(float4*)&g_psum[(base + qr) * 4]     = make_float4(ps0[0], ps0[1], ps0[2], ps0[3]);
        *(float4*)&g_psum[(base + 8 + qr) * 4] = make_float4(ps1[0], ps1[1], ps1[2], ps1[3]);
    }

    // accumulator writeback
    {
        size_t base0 = ((size_t)(sp * 2 + b) * NN + n0 + r0 + qr) * 128;
        size_t base1 = base0 + 8 * 128;
#pragma unroll
        for (int h = 0; h < 4; ++h)
#pragma unroll
            for (int n = 0; n < 4; ++n) {
                const int col = h * 32 + n * 8 + qc * 2;
                const float* c = acc[h * 4 + n];
                *(float2*)&g_part[base0 + col] = make_float2(c[0], c[1]);
                *(float2*)&g_part[base1 + col] = make_float2(c[2], c[3]);
            }
    }
}

// ---------------------------------------------------------------------------
// Kernel 3: reduce split partials, normalize, residual, LayerNorm.
// ---------------------------------------------------------------------------
__global__ __launch_bounds__(128) void k3_epi(const float* __restrict__ gamma,
                                              const float* __restrict__ beta,
                                              float*       __restrict__ out) {
    const int t  = threadIdx.x;
    const int b  = blockIdx.x >> 8;
    const int n0 = (blockIdx.x & 255) * 8;
    const int h  = t >> 5;
    const int d  = t & 31;

    __shared__ float red1[4][8], red2[4][8];

    const float gma = gamma[t];
    const float bta = beta[t];
    float ys[8];

#pragma unroll
    for (int r = 0; r < 8; ++r) {
        const int n = n0 + r;
        float accv = 0.f, rsum = 0.f;
#pragma unroll
        for (int spp = 0; spp < SPLIT; ++spp) {
            accv += g_part[(size_t)((spp * 2 + b) * NN + n) * 128 + t];
            rsum += g_psum[((size_t)(spp * 2 + b) * NN + n) * 4 + h];
        }
        float y = accv / rsum + g_h[(size_t)(b * NN + n) * 128 + t];
        ys[r] = y;
        float s1 = y, s2 = y * y;
#pragma unroll
        for (int off = 16; off; off >>= 1) {
            s1 += __shfl_xor_sync(0xffffffffu, s1, off);
            s2 += __shfl_xor_sync(0xffffffffu, s2, off);
        }
        if (d == 0) { red1[h][r] = s1; red2[h][r] = s2; }
    }
    __syncthreads();
#pragma unroll
    for (int r = 0; r < 8; ++r) {
        float s1 = red1[0][r] + red1[1][r] + red1[2][r] + red1[3][r];
        float s2 = red2[0][r] + red2[1][r] + red2[2][r] + red2[3][r];
        float mu  = s1 * (1.f / 128.f);
        float var = s2 * (1.f / 128.f) - mu * mu;
        float inv = rsqrtf(var + 1e-5f);
        out[(size_t)(b * NN + n0 + r) * 128 + t] = (ys[r] - mu) * inv * gma + bta;
    }
}

extern "C" void kernel_launch(void* const* d_in, const int* in_sizes, int n_in,
                              void* d_out, int out_size) {
    const float* x     = (const float*)d_in[0];
    const int*   adj   = (const int*)  d_in[1];
    const float* w     = (const float*)d_in[2];
    const float* a     = (const float*)d_in[3];
    const float* gamma = (const float*)d_in[4];
    const float* beta  = (const float*)d_in[5];

    static int smem_set = 0;
    if (!smem_set) {
        cudaFuncSetAttribute(k2_attn, cudaFuncAttributeMaxDynamicSharedMemorySize, SMEM_SZ);
        smem_set = 1;
    }

    k1_proj<<<512, 128>>>(x, w, a);
    k2_attn<<<16 * SPLIT * 2, 256, SMEM_SZ>>>(adj);
    k3_epi<<<512, 128>>>(gamma, beta, (float*)d_out);
}

// round 14
// speedup vs baseline: 1.8163x; 1.4986x over previous
#include <cuda_runtime.h>
#include <cuda_bf16.h>
#include <cstdint>

#define NN 2048
#define TJ 32
#define SPLIT 8
#define JCHUNK (NN / SPLIT)      // 256
#define NTILES (JCHUNK / TJ)     // 8
#define LOG2E 1.4426950408889634f

typedef unsigned long long ull;

// Scratch (device globals; no allocation allowed)
__device__ float    g_h    [2 * NN * 128];          // h[b][n][128] fp32 (residual)
__device__ uint32_t g_vb   [2 * 1024 * 128];        // vperm bf16x2 j-pairs [b][jp][col]
__device__ uint32_t g_mbits[NN * 64];               // adj bit-packed [row][j/32]
__device__ float    g_ei   [2 * NN * 4];            // pre-scaled by log2(e)
__device__ float    g_ej   [2 * NN * 4];            // pre-scaled by log2(e)
__device__ float    g_part [SPLIT * 2 * NN * 128];  // partial AV accumulators
__device__ float    g_psum [SPLIT * 2 * NN * 4];    // partial softmax denominators

__device__ __forceinline__ float ex2(float x) {
    float r;
    asm("ex2.approx.f32 %0, %1;" : "=f"(r) : "f"(x));
    return r;
}
__device__ __forceinline__ uint32_t bf16x2(float hi, float lo) {
    uint32_t r;
    asm("cvt.rn.bf16x2.f32 %0, %1, %2;" : "=r"(r) : "f"(hi), "f"(lo));
    return r;
}

// dynamic smem layout (bytes):
#define VSM_BUF (16 * 136 * 4)            // 8704 per buf (16 jp-rows x 136 u32)
#define MB_OFF  (3 * VSM_BUF)             // 26112; mask bits 128 rows x 12 u32 pitch
#define EJ_OFF  (MB_OFF + 128 * 12 * 4)   // 32256; ej 256 x float4
#define SMEM_SZ (EJ_OFF + 256 * 16)       // 36352

// ---------------------------------------------------------------------------
// Kernel 0: bit-pack adj. Warp reads 32 consecutive ints, ballot -> 1 word.
// Grid 2048 x 256 thr: block covers 64 words (8 warps x 8).
// ---------------------------------------------------------------------------
__global__ __launch_bounds__(256) void k0_pack(const int* __restrict__ adj) {
    const int wp   = threadIdx.x >> 5;
    const int lane = threadIdx.x & 31;
#pragma unroll
    for (int i = 0; i < 8; ++i) {
        int widx = blockIdx.x * 64 + wp * 8 + i;
        int row  = widx >> 6, w = widx & 63;
        int v = adj[(size_t)row * NN + w * 32 + lane];
        unsigned m = __ballot_sync(0xffffffffu, v != 0);
        if (lane == 0) g_mbits[row * 64 + w] = m;
    }
}

// ---------------------------------------------------------------------------
// Kernel 1: h = x @ w^T, scatter permuted v as bf16x2 j-pairs, ei/ej (log2e).
// ---------------------------------------------------------------------------
__global__ __launch_bounds__(128) void k1_proj(const float* __restrict__ x,
                                               const float* __restrict__ w,
                                               const float* __restrict__ a) {
    const int t    = threadIdx.x;
    const int r0   = blockIdx.x * 8;
    const int h    = t >> 5;
    const int d    = t & 31;
    const int lane = t & 31;

    __shared__ float ws[128 * 65];
    __shared__ float xs[8 * 64];

#pragma unroll
    for (int k = 0; k < 64; ++k) {
        int idx = t + k * 128;
        ws[(idx >> 6) * 65 + (idx & 63)] = w[idx];
    }
#pragma unroll
    for (int k = 0; k < 4; ++k)
        xs[t + k * 128] = x[r0 * 64 + t + k * 128];
    __syncthreads();

    const float a1v = a[h * 64 + d];
    const float a2v = a[h * 64 + 32 + d];
    const float* wrow = &ws[t * 65];

    float accv[8];
    for (int rr = 0; rr < 8; ++rr) {
        const int row = r0 + rr;
        float acc = 0.f;
#pragma unroll
        for (int i = 0; i < 64; ++i)
            acc += xs[rr * 64 + i] * wrow[i];
        accv[rr] = acc;
        g_h[row * 128 + t] = acc;

        float p1 = acc * a1v;
        float p2 = acc * a2v;
#pragma unroll
        for (int off = 16; off; off >>= 1) {
            p1 += __shfl_xor_sync(0xffffffffu, p1, off);
            p2 += __shfl_xor_sync(0xffffffffu, p2, off);
        }
        if (lane == 0) {
            g_ei[row * 4 + h] = p1 * LOG2E;
            g_ej[row * 4 + h] = p2 * LOG2E;
        }
    }

    // vb pack: idx = h*NN + n0 + rr; pair rows (2jp,2jp+1) <- rr and rr+4
    const int b  = r0 >> 11;
    const int n0 = r0 & (NN - 1);
    const int jp = (h * NN + n0) >> 3;
#pragma unroll
    for (int rr = 0; rr < 4; ++rr)
        g_vb[(size_t)(b * 1024 + jp) * 128 + rr * 32 + d] = bf16x2(accv[rr + 4], accv[rr]);
}

// ---------------------------------------------------------------------------
// Kernel 2: attention via bf16 mma.sync.m16n8k16, 3-deep cp.async pipeline.
// Grid 256 = sp(8) x nt(16) x b(2), 256 threads = 8 warps x 16 rows.
// Mask bits + ej staged once per chunk; per-tile async = V only (8.7KB).
// ---------------------------------------------------------------------------
__global__ __launch_bounds__(256, 2) void k2_attn() {
    extern __shared__ __align__(16) char smem[];
    const int t  = threadIdx.x;
    const int wp = t >> 5;
    const int qr = (t & 31) >> 2;
    const int qc = t & 3;
    const int sp = blockIdx.x & 7;
    const int nt = (blockIdx.x >> 3) & 15;
    const int b  = blockIdx.x >> 7;
    const int n0 = nt * 128;
    const int js = sp * JCHUNK;
    const int r0 = wp * 16;

    const float4 eiA = *(const float4*)&g_ei[(size_t)(b * NN + n0 + r0 + qr) * 4];
    const float4 eiB = *(const float4*)&g_ei[(size_t)(b * NN + n0 + r0 + 8 + qr) * 4];

    float acc[16][4];
#pragma unroll
    for (int i = 0; i < 16; ++i)
#pragma unroll
        for (int j = 0; j < 4; ++j) acc[i][j] = 0.f;
    float ps0[4], ps1[4];
#pragma unroll
    for (int h = 0; h < 4; ++h) { ps0[h] = 0.f; ps1[h] = 0.f; }

    uint32_t sbase;
    asm("{ .reg .u64 u; cvta.to.shared.u64 u, %1; cvt.u32.u64 %0, u; }" : "=r"(sbase) : "l"(smem));

    // V tile loader: 16 jp-rows x 512B (2 x 16B per thread)
    auto issueV = [&](int tile) {
        const int jp0 = (js + tile * TJ) >> 1;
        const uint32_t vbase = sbase + (tile % 3) * VSM_BUF;
#pragma unroll
        for (int k = 0; k < 2; ++k) {
            int c = t + k * 256;            // 0..511
            int row = c >> 5, o = c & 31;
            uint32_t dst = vbase + row * 544 + o * 16;
            const uint32_t* src = g_vb + (size_t)(b * 1024 + jp0 + row) * 128 + o * 4;
            asm volatile("cp.async.cg.shared.global [%0], [%1], 16;" :: "r"(dst), "l"(src));
        }
        asm volatile("cp.async.commit_group;");
    };

    // upfront: mask bits (128 rows x 8 words, pitch 12) + ej chunk (256 x f4)
    {
        const int row = t >> 1, half = t & 1;
        uint32_t dst = sbase + MB_OFF + row * 48 + half * 16;
        const uint32_t* src = g_mbits + (size_t)(n0 + row) * 64 + (js >> 5) + half * 4;
        asm volatile("cp.async.cg.shared.global [%0], [%1], 16;" :: "r"(dst), "l"(src));
        uint32_t dst2 = sbase + EJ_OFF + t * 16;
        const float* src2 = g_ej + (size_t)(b * NN + js + t) * 4;
        asm volatile("cp.async.cg.shared.global [%0], [%1], 16;" :: "r"(dst2), "l"(src2));
    }
    issueV(0);   // group 0 = upfront + V0
    issueV(1);
    issueV(2);

    const uint32_t* mb  = (const uint32_t*)(smem + MB_OFF);
    const float4*  ejs4 = (const float4*)(smem + EJ_OFF);

    for (int tile = 0; tile < NTILES; ++tile) {
        asm volatile("cp.async.wait_group 2;" ::: "memory");
        __syncthreads();
        const uint32_t* vb = (const uint32_t*)(smem + (tile % 3) * VSM_BUF);

        const uint32_t wA = mb[(r0 + qr) * 12 + tile];
        const uint32_t wB = mb[(r0 + 8 + qr) * 12 + tile];

#pragma unroll
        for (int ks = 0; ks < 2; ++ks) {
            const int jb = ks * 16;
            const int b0 = jb + 2 * qc;
            const float pmA0 = (float)((wA >> b0) & 1u);
            const float pmA1 = (float)((wA >> (b0 + 1)) & 1u);
            const float pmA2 = (float)((wA >> (b0 + 8)) & 1u);
            const float pmA3 = (float)((wA >> (b0 + 9)) & 1u);
            const float pmB0 = (float)((wB >> b0) & 1u);
            const float pmB1 = (float)((wB >> (b0 + 1)) & 1u);
            const float pmB2 = (float)((wB >> (b0 + 8)) & 1u);
            const float pmB3 = (float)((wB >> (b0 + 9)) & 1u);
            const float4 ej0 = ejs4[tile * 32 + jb + 2 * qc];
            const float4 ej1 = ejs4[tile * 32 + jb + 2 * qc + 1];
            const float4 ej2 = ejs4[tile * 32 + jb + 2 * qc + 8];
            const float4 ej3 = ejs4[tile * 32 + jb + 2 * qc + 9];
#pragma unroll
            for (int h = 0; h < 4; ++h) {
                const float ei0 = (&eiA.x)[h], ei1 = (&eiB.x)[h];
                const float ejv0 = (&ej0.x)[h], ejv1 = (&ej1.x)[h];
                const float ejv2 = (&ej2.x)[h], ejv3 = (&ej3.x)[h];
                float e;
                float pA0, pA1, pA2, pA3, pB0, pB1, pB2, pB3;
                e = ei0 + ejv0; e = fmaxf(e, 0.2f * e); pA0 = ex2(e) * pmA0;
                e = ei0 + ejv1; e = fmaxf(e, 0.2f * e); pA1 = ex2(e) * pmA1;
                e = ei0 + ejv2; e = fmaxf(e, 0.2f * e); pA2 = ex2(e) * pmA2;
                e = ei0 + ejv3; e = fmaxf(e, 0.2f * e); pA3 = ex2(e) * pmA3;
                e = ei1 + ejv0; e = fmaxf(e, 0.2f * e); pB0 = ex2(e) * pmB0;
                e = ei1 + ejv1; e = fmaxf(e, 0.2f * e); pB1 = ex2(e) * pmB1;
                e = ei1 + ejv2; e = fmaxf(e, 0.2f * e); pB2 = ex2(e) * pmB2;
                e = ei1 + ejv3; e = fmaxf(e, 0.2f * e); pB3 = ex2(e) * pmB3;
                ps0[h] += (pA0 + pA1) + (pA2 + pA3);
                ps1[h] += (pB0 + pB1) + (pB2 + pB3);
                const uint32_t a0 = bf16x2(pA1, pA0);
                const uint32_t a1 = bf16x2(pB1, pB0);
                const uint32_t a2 = bf16x2(pA3, pA2);
                const uint32_t a3 = bf16x2(pB3, pB2);
#pragma unroll
                for (int n = 0; n < 4; ++n) {
                    const int col = h * 32 + n * 8 + qr;
                    const uint32_t v0 = vb[(ks * 8 + qc) * 136 + col];
                    const uint32_t v1 = vb[(ks * 8 + qc + 4) * 136 + col];
                    float* c = acc[h * 4 + n];
                    asm("mma.sync.aligned.m16n8k16.row.col.f32.bf16.bf16.f32 "
                        "{%0,%1,%2,%3}, {%4,%5,%6,%7}, {%8,%9}, {%0,%1,%2,%3};"
                        : "+f"(c[0]), "+f"(c[1]), "+f"(c[2]), "+f"(c[3])
                        : "r"(a0), "r"(a1), "r"(a2), "r"(a3), "r"(v0), "r"(v1));
                }
            }
        }
        __syncthreads();                    // all reads of buf tile%3 done
        if (tile + 3 < NTILES) issueV(tile + 3);
    }

    // psum: reduce over qc (lanes cover disjoint j)
#pragma unroll
    for (int h = 0; h < 4; ++h) {
        ps0[h] += __shfl_xor_sync(0xffffffffu, ps0[h], 1);
        ps0[h] += __shfl_xor_sync(0xffffffffu, ps0[h], 2);
        ps1[h] += __shfl_xor_sync(0xffffffffu, ps1[h], 1);
        ps1[h] += __shfl_xor_sync(0xffffffffu, ps1[h], 2);
    }
    if (qc == 0) {
        size_t base = ((size_t)(sp * 2 + b) * NN + n0 + r0);
        *(float4*)&g_psum[(base + qr) * 4]     = make_float4(ps0[0], ps0[1], ps0[2], ps0[3]);
        *(float4*)&g_psum[(base + 8 + qr) * 4] = make_float4(ps1[0], ps1[1], ps1[2], ps1[3]);
    }

    // accumulator writeback
    {
        size_t base0 = ((size_t)(sp * 2 + b) * NN + n0 + r0 + qr) * 128;
        size_t base1 = base0 + 8 * 128;
#pragma unroll
        for (int h = 0; h < 4; ++h)
#pragma unroll
            for (int n = 0; n < 4; ++n) {
                const int col = h * 32 + n * 8 + qc * 2;
                const float* c = acc[h * 4 + n];
                *(float2*)&g_part[base0 + col] = make_float2(c[0], c[1]);
                *(float2*)&g_part[base1 + col] = make_float2(c[2], c[3]);
            }
    }
}

// ---------------------------------------------------------------------------
// Kernel 3: reduce split partials, normalize, residual, LayerNorm.
// Grid 2048 = b(2) x 1024 tiles of 2 rows; 128 threads (thread = column).
// ---------------------------------------------------------------------------
__global__ __launch_bounds__(128) void k3_epi(const float* __restrict__ gamma,
                                              const float* __restrict__ beta,
                                              float*       __restrict__ out) {
    const int t  = threadIdx.x;
    const int b  = blockIdx.x >> 10;
    const int n0 = (blockIdx.x & 1023) * 2;
    const int h  = t >> 5;
    const int d  = t & 31;

    __shared__ float red1[4][2], red2[4][2];

    const float gma = gamma[t];
    const float bta = beta[t];
    float ys[2];

#pragma unroll
    for (int r = 0; r < 2; ++r) {
        const int n = n0 + r;
        float accv = 0.f, rsum = 0.f;
#pragma unroll
        for (int spp = 0; spp < SPLIT; ++spp) {
            accv += g_part[(size_t)((spp * 2 + b) * NN + n) * 128 + t];
            rsum += g_psum[((size_t)(spp * 2 + b) * NN + n) * 4 + h];
        }
        float y = accv / rsum + g_h[(size_t)(b * NN + n) * 128 + t];
        ys[r] = y;
        float s1 = y, s2 = y * y;
#pragma unroll
        for (int off = 16; off; off >>= 1) {
            s1 += __shfl_xor_sync(0xffffffffu, s1, off);
            s2 += __shfl_xor_sync(0xffffffffu, s2, off);
        }
        if (d == 0) { red1[h][r] = s1; red2[h][r] = s2; }
    }
    __syncthreads();
#pragma unroll
    for (int r = 0; r < 2; ++r) {
        float s1 = red1[0][r] + red1[1][r] + red1[2][r] + red1[3][r];
        float s2 = red2[0][r] + red2[1][r] + red2[2][r] + red2[3][r];
        float mu  = s1 * (1.f / 128.f);
        float var = s2 * (1.f / 128.f) - mu * mu;
        float inv = rsqrtf(var + 1e-5f);
        out[(size_t)(b * NN + n0 + r) * 128 + t] = (ys[r] - mu) * inv * gma + bta;
    }
}

extern "C" void kernel_launch(void* const* d_in, const int* in_sizes, int n_in,
                              void* d_out, int out_size) {
    const float* x     = (const float*)d_in[0];
    const int*   adj   = (const int*)  d_in[1];
    const float* w     = (const float*)d_in[2];
    const float* a     = (const float*)d_in[3];
    const float* gamma = (const float*)d_in[4];
    const float* beta  = (const float*)d_in[5];

    static int smem_set = 0;
    if (!smem_set) {
        cudaFuncSetAttribute(k2_attn, cudaFuncAttributeMaxDynamicSharedMemorySize, SMEM_SZ);
        smem_set = 1;
    }

    k0_pack<<<2048, 256>>>(adj);
    k1_proj<<<512, 128>>>(x, w, a);
    k2_attn<<<16 * SPLIT * 2, 256, SMEM_SZ>>>();
    k3_epi<<<2048, 128>>>(gamma, beta, (float*)d_out);
}